// round 16
// baseline (speedup 1.0000x reference)
#include <cuda_runtime.h>
#include <math.h>

#define NMAX 8192
#define NTHR 128
#define QPER 4
#define QTILE (NTHR * QPER)    // 512 queries per block
#define JTILE 128              // DB points per slab (2 KB tiles)
#define JGRP 16                // group size; 4-bit local index in mantissa
#define NGRP (JTILE / JGRP)
#define JBMAX 64               // max DB slabs (8192/128)

// Scratch (allocation-free rule): per-(dir, jblock) partial min keys.
// key = (dist2_bits << 32) | sigma_bits   (both non-negative floats).
__device__ unsigned long long g_keys[2][JBMAX][NMAX];
__device__ float g_sums[64];

static __device__ __forceinline__ float3 get_pt(
        const float* __restrict__ P, int i, bool doT,
        const float* __restrict__ T) {
    float x = __ldg(P + 3*i), y = __ldg(P + 3*i + 1), z = __ldg(P + 3*i + 2);
    if (doT) {
        return make_float3(
            fmaf(T[0], x, fmaf(T[1], y, fmaf(T[2],  z, T[3]))),
            fmaf(T[4], x, fmaf(T[5], y, fmaf(T[6],  z, T[7]))),
            fmaf(T[8], x, fmaf(T[9], y, fmaf(T[10], z, T[11]))));
    }
    return make_float3(x, y, z);
}

// One 16-j group: 3 FFMA + LOP3 + FMNMX per pair; index in low 4 mantissa bits.
static __device__ __forceinline__ void group_min(
        const float4* __restrict__ sBt, int g,
        const float* ax, const float* ay, const float* az,
        float* bestv, int* bestg) {
    float e0[QPER], e1[QPER];
#pragma unroll
    for (int q = 0; q < QPER; q++) { e0[q] = 3.4e38f; e1[q] = 3.4e38f; }
#pragma unroll
    for (int u = 0; u < JGRP; u++) {
        float4 b = sBt[g * JGRP + u];   // uniform broadcast LDS.128
#pragma unroll
        for (int q = 0; q < QPER; q++) {
            float d = fmaf(ax[q], b.x, fmaf(ay[q], b.y, fmaf(az[q], b.z, b.w)));
            float dk = __uint_as_float((__float_as_uint(d) & ~15u) | (unsigned)u);
            if (u & 1) e1[q] = fminf(e1[q], dk);
            else       e0[q] = fminf(e0[q], dk);
        }
    }
#pragma unroll
    for (int q = 0; q < QPER; q++) {
        float gm = fminf(e0[q], e1[q]);
        if (gm < bestv[q]) { bestv[q] = gm; bestg[q] = g; }
    }
}

// blockIdx.z: 0 => queries=ref, DB=transformed src. 1 => swapped.
// Metric: d' = |b|^2 - 2 a.b (query-constant |a|^2 dropped: argmin-safe).
__global__ void __launch_bounds__(NTHR) nn_sweep(
        const float* __restrict__ ref, const float* __restrict__ src,
        const float* __restrict__ T,
        const float* __restrict__ rsig, const float* __restrict__ ssig,
        int n, int m) {
    const int dir = blockIdx.z;
    const float* Apts = dir ? src : ref;
    const float* Bpts = dir ? ref : src;
    const float* Bsig = dir ? rsig : ssig;
    const int nA = dir ? m : n;
    const int nB = dir ? n : m;
    const bool xfA = (dir == 1), xfB = (dir == 0);

    __shared__ float4 sBt[JTILE];   // (-2x, -2y, -2z, |b|^2)
    __shared__ float4 sBo[JTILE];   // (x, y, z, sigma) for exact epilogue
    const int tid = threadIdx.x;
    const int jbase = blockIdx.y * JTILE;

    if (tid < JTILE) {
        int gj = jbase + tid;
        float3 p = (gj < nB) ? get_pt(Bpts, gj, xfB, T)
                             : make_float3(1e15f, 1e15f, 1e15f);
        float s = (gj < nB) ? __ldg(Bsig + gj) : 1.0f;
        sBo[tid] = make_float4(p.x, p.y, p.z, s);
        float b2 = fmaf(p.x, p.x, fmaf(p.y, p.y, p.z * p.z));
        sBt[tid] = make_float4(-2.0f * p.x, -2.0f * p.y, -2.0f * p.z, b2);
    }

    float ax[QPER], ay[QPER], az[QPER], bestv[QPER];
    int bestg[QPER];
    const int q0 = blockIdx.x * QTILE + tid;
#pragma unroll
    for (int q = 0; q < QPER; q++) {
        int qi = q0 + q * NTHR;
        float3 a = (qi < nA) ? get_pt(Apts, qi, xfA, T)
                             : make_float3(0.f, 0.f, 0.f);
        ax[q] = a.x; ay[q] = a.y; az[q] = a.z;
        bestv[q] = 3.4e38f; bestg[q] = 0;
    }
    __syncthreads();

    // group loop, manually paired (x2) to overlap merge chains across groups
#pragma unroll 1
    for (int g = 0; g < NGRP; g += 2) {
        group_min(sBt, g,     ax, ay, az, bestv, bestg);
        group_min(sBt, g + 1, ax, ay, az, bestv, bestg);
    }

    // Recovery is arithmetic only: j = 16*bestg + low-4-bits(bestv). Exact d^2.
#pragma unroll
    for (int q = 0; q < QPER; q++) {
        int qi = q0 + q * NTHR;
        if (qi < nA) {
            int bj = bestg[q] * JGRP + (int)(__float_as_uint(bestv[q]) & 15u);
            float4 b = sBo[bj];
            float dx = ax[q] - b.x, dy = ay[q] - b.y, dz = az[q] - b.z;
            float d2 = fmaf(dx, dx, fmaf(dy, dy, dz * dz));
            unsigned long long key =
                (((unsigned long long)__float_as_uint(d2)) << 32) |
                (unsigned long long)__float_as_uint(b.w);
            g_keys[dir][blockIdx.y][qi] = key;   // no atomics
        }
    }
}

// Stage 1: one thread per query (fwd then bwd concatenated); scan slab partials
// with 4 independent accumulators (MLP to hide memory latency).
__global__ void __launch_bounds__(256) loss_stage1(
        const float* __restrict__ rsig, const float* __restrict__ ssig,
        int n, int m) {
    __shared__ float wsum[8];
    int idx = blockIdx.x * 256 + threadIdx.x;
    float acc = 0.0f;
    if (idx < n + m) {
        int dir = (idx < n) ? 0 : 1;
        int i = (idx < n) ? idx : idx - n;
        int nB = dir ? n : m;
        int njb = (nB + JTILE - 1) / JTILE;
        const unsigned long long* col = &g_keys[dir][0][i];
        unsigned long long kk[4] = {~0ULL, ~0ULL, ~0ULL, ~0ULL};
        int jb = 0;
        for (; jb + 4 <= njb; jb += 4) {
#pragma unroll
            for (int t = 0; t < 4; t++) {
                unsigned long long v = col[(jb + t) * NMAX];
                kk[t] = (v < kk[t]) ? v : kk[t];
            }
        }
        for (; jb < njb; jb++) {
            unsigned long long v = col[jb * NMAX];
            kk[0] = (v < kk[0]) ? v : kk[0];
        }
        unsigned long long ka = (kk[0] < kk[1]) ? kk[0] : kk[1];
        unsigned long long kb = (kk[2] < kk[3]) ? kk[2] : kk[3];
        unsigned long long k = (ka < kb) ? ka : kb;
        float self = dir ? __ldg(ssig + i) : __ldg(rsig + i);
        float d   = sqrtf(__uint_as_float((unsigned)(k >> 32)));
        float sig = 0.5f * (self + __uint_as_float((unsigned)k));
        float inv = dir ? (1.0f / (float)m) : (1.0f / (float)n);
        acc = (__logf(sig) + __fdividef(d, sig)) * inv;
    }
#pragma unroll
    for (int o = 16; o > 0; o >>= 1)
        acc += __shfl_xor_sync(0xFFFFFFFF, acc, o);
    if ((threadIdx.x & 31) == 0) wsum[threadIdx.x >> 5] = acc;
    __syncthreads();
    if (threadIdx.x < 8) {
        float v = wsum[threadIdx.x];
#pragma unroll
        for (int o = 4; o > 0; o >>= 1)
            v += __shfl_xor_sync(0xFF, v, o);
        if (threadIdx.x == 0) g_sums[blockIdx.x] = v;
    }
}

__global__ void loss_stage2(float* __restrict__ out, int nblocks) {
    int tid = threadIdx.x;   // 64 threads
    __shared__ float s2[2];
    float v = (tid < nblocks) ? g_sums[tid] : 0.0f;
#pragma unroll
    for (int o = 16; o > 0; o >>= 1)
        v += __shfl_xor_sync(0xFFFFFFFF, v, o);
    if ((tid & 31) == 0) s2[tid >> 5] = v;
    __syncthreads();
    if (tid == 0) out[0] = s2[0] + s2[1];
}

extern "C" void kernel_launch(void* const* d_in, const int* in_sizes, int n_in,
                              void* d_out, int out_size) {
    const float* ref  = (const float*)d_in[0];
    const float* src  = (const float*)d_in[1];
    const float* T    = (const float*)d_in[2];
    const float* rsig = (const float*)d_in[3];
    const float* ssig = (const float*)d_in[4];
    int n = in_sizes[3];
    int m = in_sizes[4];

    int nm = n > m ? n : m;
    dim3 g((nm + QTILE - 1) / QTILE, (nm + JTILE - 1) / JTILE, 2);
    nn_sweep<<<g, NTHR>>>(ref, src, T, rsig, ssig, n, m);

    int rblocks = (n + m + 255) / 256;
    loss_stage1<<<rblocks, 256>>>(rsig, ssig, n, m);
    loss_stage2<<<1, 64>>>((float*)d_out, rblocks);
}

// round 17
// speedup vs baseline: 1.0528x; 1.0528x over previous
#include <cuda_runtime.h>
#include <math.h>

#define NMAX 8192
#define NTHR 128
#define QPER 4                 // 4 query chains = 2 packed f32x2 chains
#define NCH (QPER / 2)
#define QTILE (NTHR * QPER)    // 512 queries per block
#define JTILE 256              // DB points per slab
#define JGRP 16                // group size; 4-bit local index in mantissa
#define NGRP (JTILE / JGRP)
#define JBMAX 32               // max DB slabs (8192/256)

// Scratch (allocation-free rule): per-(dir, jblock) partial min keys.
// key = (dist2_bits << 32) | sigma_bits   (both non-negative floats).
__device__ unsigned long long g_keys[2][JBMAX][NMAX];
__device__ float g_sums[64];

static __device__ __forceinline__ unsigned long long pack2(float lo, float hi) {
    unsigned long long r;
    asm("mov.b64 %0, {%1, %2};" : "=l"(r) : "f"(lo), "f"(hi));
    return r;
}
static __device__ __forceinline__ unsigned long long fma2(
        unsigned long long a, unsigned long long b, unsigned long long c) {
    unsigned long long r;
    asm("fma.rn.f32x2 %0, %1, %2, %3;" : "=l"(r) : "l"(a), "l"(b), "l"(c));
    return r;
}
static __device__ __forceinline__ void unpack2(unsigned long long v,
                                               float& lo, float& hi) {
    asm("mov.b64 {%0, %1}, %2;" : "=f"(lo), "=f"(hi) : "l"(v));
}

static __device__ __forceinline__ float3 get_pt(
        const float* __restrict__ P, int i, bool doT,
        const float* __restrict__ T) {
    float x = __ldg(P + 3*i), y = __ldg(P + 3*i + 1), z = __ldg(P + 3*i + 2);
    if (doT) {
        return make_float3(
            fmaf(T[0], x, fmaf(T[1], y, fmaf(T[2],  z, T[3]))),
            fmaf(T[4], x, fmaf(T[5], y, fmaf(T[6],  z, T[7]))),
            fmaf(T[8], x, fmaf(T[9], y, fmaf(T[10], z, T[11]))));
    }
    return make_float3(x, y, z);
}

// blockIdx.z: 0 => queries=ref, DB=transformed src. 1 => swapped.
// Metric: d' = |b|^2 - 2 a.b (query-constant |a|^2 dropped: argmin-safe).
// Hot loop: FFMA2 packs 2 query chains per instr (3 FFMA2 / 2 pairs);
// per pair: 1 LOP3 (embed 4-bit group-local index) + 1 FMNMX.
__global__ void __launch_bounds__(NTHR) nn_sweep(
        const float* __restrict__ ref, const float* __restrict__ src,
        const float* __restrict__ T,
        const float* __restrict__ rsig, const float* __restrict__ ssig,
        int n, int m) {
    const int dir = blockIdx.z;
    const float* Apts = dir ? src : ref;
    const float* Bpts = dir ? ref : src;
    const float* Bsig = dir ? rsig : ssig;
    const int nA = dir ? m : n;
    const int nB = dir ? n : m;
    const bool xfA = (dir == 1), xfB = (dir == 0);

    __shared__ ulonglong2 sBp[JTILE * 2];  // [(−2x,−2x),(−2y,−2y)],[(−2z,−2z),(b2,b2)]
    __shared__ float4 sBo[JTILE];          // (x, y, z, sigma) for exact epilogue
    const int tid = threadIdx.x;
    const int jbase = blockIdx.y * JTILE;

    for (int j = tid; j < JTILE; j += NTHR) {
        int gj = jbase + j;
        float3 p = (gj < nB) ? get_pt(Bpts, gj, xfB, T)
                             : make_float3(1e15f, 1e15f, 1e15f);
        float s = (gj < nB) ? __ldg(Bsig + gj) : 1.0f;
        sBo[j] = make_float4(p.x, p.y, p.z, s);
        float nx = -2.0f * p.x, ny = -2.0f * p.y, nz = -2.0f * p.z;
        float b2 = fmaf(p.x, p.x, fmaf(p.y, p.y, p.z * p.z));
        sBp[2*j + 0] = make_ulonglong2(pack2(nx, nx), pack2(ny, ny));
        sBp[2*j + 1] = make_ulonglong2(pack2(nz, nz), pack2(b2, b2));
    }

    unsigned long long axp[NCH], ayp[NCH], azp[NCH];
    float bestv[QPER];
    int bestg[QPER];
    const int q0 = blockIdx.x * QTILE + tid;
#pragma unroll
    for (int c = 0; c < NCH; c++) {
        int qi0 = q0 + (2*c + 0) * NTHR;
        int qi1 = q0 + (2*c + 1) * NTHR;
        float3 a0 = (qi0 < nA) ? get_pt(Apts, qi0, xfA, T) : make_float3(0.f, 0.f, 0.f);
        float3 a1 = (qi1 < nA) ? get_pt(Apts, qi1, xfA, T) : make_float3(0.f, 0.f, 0.f);
        axp[c] = pack2(a0.x, a1.x);
        ayp[c] = pack2(a0.y, a1.y);
        azp[c] = pack2(a0.z, a1.z);
        bestv[2*c] = 3.4e38f; bestv[2*c+1] = 3.4e38f;
        bestg[2*c] = 0;       bestg[2*c+1] = 0;
    }
    __syncthreads();

#pragma unroll 1
    for (int g = 0; g < NGRP; g++) {
        float e0[QPER], e1[QPER];   // alternating accumulators per chain
#pragma unroll
        for (int q = 0; q < QPER; q++) { e0[q] = 3.4e38f; e1[q] = 3.4e38f; }
#pragma unroll
        for (int u = 0; u < JGRP; u++) {
            ulonglong2 u0 = sBp[2*(g*JGRP + u) + 0];  // (−2x,−2x),(−2y,−2y)
            ulonglong2 u1 = sBp[2*(g*JGRP + u) + 1];  // (−2z,−2z),(b2,b2)
#pragma unroll
            for (int c = 0; c < NCH; c++) {
                unsigned long long t = fma2(azp[c], u1.x, u1.y);
                t = fma2(ayp[c], u0.y, t);
                t = fma2(axp[c], u0.x, t);
                float d0, d1;
                unpack2(t, d0, d1);   // register aliasing, no SASS
                float dk0 = __uint_as_float((__float_as_uint(d0) & ~15u) | (unsigned)u);
                float dk1 = __uint_as_float((__float_as_uint(d1) & ~15u) | (unsigned)u);
                if (u & 1) {
                    e1[2*c + 0] = fminf(e1[2*c + 0], dk0);
                    e1[2*c + 1] = fminf(e1[2*c + 1], dk1);
                } else {
                    e0[2*c + 0] = fminf(e0[2*c + 0], dk0);
                    e0[2*c + 1] = fminf(e0[2*c + 1], dk1);
                }
            }
        }
#pragma unroll
        for (int q = 0; q < QPER; q++) {
            float gm = fminf(e0[q], e1[q]);
            if (gm < bestv[q]) { bestv[q] = gm; bestg[q] = g; }
        }
    }

    // Recovery is arithmetic only: j = 16*bestg + low-4-bits(bestv). Exact d^2.
#pragma unroll
    for (int c = 0; c < NCH; c++) {
        float ax0, ax1, ay0, ay1, az0, az1;
        unpack2(axp[c], ax0, ax1);
        unpack2(ayp[c], ay0, ay1);
        unpack2(azp[c], az0, az1);
#pragma unroll
        for (int h = 0; h < 2; h++) {
            int q = 2*c + h;
            int qi = q0 + q * NTHR;
            if (qi < nA) {
                float qx = h ? ax1 : ax0, qy = h ? ay1 : ay0, qz = h ? az1 : az0;
                int bj = bestg[q] * JGRP + (int)(__float_as_uint(bestv[q]) & 15u);
                float4 b = sBo[bj];
                float dx = qx - b.x, dy = qy - b.y, dz = qz - b.z;
                float d2 = fmaf(dx, dx, fmaf(dy, dy, dz * dz));
                unsigned long long key =
                    (((unsigned long long)__float_as_uint(d2)) << 32) |
                    (unsigned long long)__float_as_uint(b.w);
                g_keys[dir][blockIdx.y][qi] = key;   // no atomics
            }
        }
    }
}

// Stage 1: one thread per query (fwd then bwd concatenated); scan slab partials
// with 4 independent accumulators (MLP to hide memory latency).
__global__ void __launch_bounds__(256) loss_stage1(
        const float* __restrict__ rsig, const float* __restrict__ ssig,
        int n, int m) {
    __shared__ float wsum[8];
    int idx = blockIdx.x * 256 + threadIdx.x;
    float acc = 0.0f;
    if (idx < n + m) {
        int dir = (idx < n) ? 0 : 1;
        int i = (idx < n) ? idx : idx - n;
        int nB = dir ? n : m;
        int njb = (nB + JTILE - 1) / JTILE;
        const unsigned long long* col = &g_keys[dir][0][i];
        unsigned long long kk[4] = {~0ULL, ~0ULL, ~0ULL, ~0ULL};
        int jb = 0;
        for (; jb + 4 <= njb; jb += 4) {
#pragma unroll
            for (int t = 0; t < 4; t++) {
                unsigned long long v = col[(jb + t) * NMAX];
                kk[t] = (v < kk[t]) ? v : kk[t];
            }
        }
        for (; jb < njb; jb++) {
            unsigned long long v = col[jb * NMAX];
            kk[0] = (v < kk[0]) ? v : kk[0];
        }
        unsigned long long ka = (kk[0] < kk[1]) ? kk[0] : kk[1];
        unsigned long long kb = (kk[2] < kk[3]) ? kk[2] : kk[3];
        unsigned long long k = (ka < kb) ? ka : kb;
        float self = dir ? __ldg(ssig + i) : __ldg(rsig + i);
        float d   = sqrtf(__uint_as_float((unsigned)(k >> 32)));
        float sig = 0.5f * (self + __uint_as_float((unsigned)k));
        float inv = dir ? (1.0f / (float)m) : (1.0f / (float)n);
        acc = (__logf(sig) + __fdividef(d, sig)) * inv;
    }
#pragma unroll
    for (int o = 16; o > 0; o >>= 1)
        acc += __shfl_xor_sync(0xFFFFFFFF, acc, o);
    if ((threadIdx.x & 31) == 0) wsum[threadIdx.x >> 5] = acc;
    __syncthreads();
    if (threadIdx.x < 8) {
        float v = wsum[threadIdx.x];
#pragma unroll
        for (int o = 4; o > 0; o >>= 1)
            v += __shfl_xor_sync(0xFF, v, o);
        if (threadIdx.x == 0) g_sums[blockIdx.x] = v;
    }
}

__global__ void loss_stage2(float* __restrict__ out, int nblocks) {
    int tid = threadIdx.x;   // 64 threads
    __shared__ float s2[2];
    float v = (tid < nblocks) ? g_sums[tid] : 0.0f;
#pragma unroll
    for (int o = 16; o > 0; o >>= 1)
        v += __shfl_xor_sync(0xFFFFFFFF, v, o);
    if ((tid & 31) == 0) s2[tid >> 5] = v;
    __syncthreads();
    if (tid == 0) out[0] = s2[0] + s2[1];
}

extern "C" void kernel_launch(void* const* d_in, const int* in_sizes, int n_in,
                              void* d_out, int out_size) {
    const float* ref  = (const float*)d_in[0];
    const float* src  = (const float*)d_in[1];
    const float* T    = (const float*)d_in[2];
    const float* rsig = (const float*)d_in[3];
    const float* ssig = (const float*)d_in[4];
    int n = in_sizes[3];
    int m = in_sizes[4];

    int nm = n > m ? n : m;
    dim3 g((nm + QTILE - 1) / QTILE, (nm + JTILE - 1) / JTILE, 2);
    nn_sweep<<<g, NTHR>>>(ref, src, T, rsig, ssig, n, m);

    int rblocks = (n + m + 255) / 256;
    loss_stage1<<<rblocks, 256>>>(rsig, ssig, n, m);
    loss_stage2<<<1, 64>>>((float*)d_out, rblocks);
}